// round 1
// baseline (speedup 1.0000x reference)
#include <cuda_runtime.h>

#define N_LEAVES   16384
#define DIM        512
#define DEPTH      14
#define K          5                      // subtree depth per block -> 32 leaves
#define LPB        (1 << K)               // 32 leaves per block
#define NBLOCKS    (N_LEAVES / LPB)       // 512
#define ROOT_LEVEL (DEPTH - K)            // 9
#define N_UPPER    ((1 << ROOT_LEVEL) - 1) // 511 nodes at levels 0..8
#define MIN_DIST   1e-7f

__device__ double g_acc;

__global__ void tm_init_kernel() { g_acc = 0.0; }

// Levels 0..ROOT_LEVEL-1 (nodes 0..510): sq and branch terms, one warp per node.
__global__ void tm_upper_kernel(const float* __restrict__ deltas,
                                const float* __restrict__ heights) {
    int gwarp = (blockIdx.x * blockDim.x + threadIdx.x) >> 5;
    int lane  = threadIdx.x & 31;
    if (gwarp >= N_UPPER) return;
    int node = gwarp;
    const float4* row = (const float4*)(deltas + (size_t)node * DIM);
    float s = 0.f;
    #pragma unroll
    for (int c = 0; c < 4; c++) {
        float4 v = row[lane + 32 * c];
        s += v.x * v.x + v.y * v.y + v.z * v.z + v.w * v.w;
    }
    #pragma unroll
    for (int off = 16; off; off >>= 1) s += __shfl_down_sync(0xffffffffu, s, off);
    if (lane == 0) {
        double term;
        if (node == 0) {
            term = (double)s;
        } else {
            float br = fmaxf(heights[node] - heights[(node - 1) >> 1], MIN_DIST);
            term = (double)(s / br);
        }
        atomicAdd(&g_acc, term);
    }
}

// Stack update: load delta row of node at tree level (DEPTH-B) on leaf i's path,
// DST = BASE + delta, and accumulate fused sq/branch term.
#define UPD(B, BASE, DST) do {                                                   \
    int node = (i >> (B)) + ((1 << (DEPTH - (B))) - 1);                          \
    float4 d = ((const float4*)(deltas + (size_t)node * DIM))[tid];              \
    DST.x = BASE.x + d.x; DST.y = BASE.y + d.y;                                  \
    DST.z = BASE.z + d.z; DST.w = BASE.w + d.w;                                  \
    float br = fmaxf(heights[node] - heights[(node - 1) >> 1], MIN_DIST);        \
    acc += (double)((d.x * d.x + d.y * d.y + d.z * d.z + d.w * d.w) / br);       \
} while (0)

__global__ void __launch_bounds__(128)
tm_main_kernel(const float* __restrict__ x,
               const float* __restrict__ deltas,
               const float* __restrict__ heights,
               float* __restrict__ out) {
    __shared__ float  pd[LPB * 128];   // deferred per-leaf dot partials (16 KB)
    __shared__ double sacc[4];

    const int tid = threadIdx.x;       // owns float4 slice [tid*4, tid*4+4)
    const int bi  = blockIdx.x;        // subtree index (level-9 node = bi + 511)
    double acc = 0.0;

    // Common path: levels 0..ROOT_LEVEL summed once into registers.
    float4 wc = make_float4(0.f, 0.f, 0.f, 0.f);
    #pragma unroll
    for (int l = 0; l <= ROOT_LEVEL; l++) {
        int node = (bi >> (ROOT_LEVEL - l)) + ((1 << l) - 1);
        float4 d = ((const float4*)(deltas + (size_t)node * DIM))[tid];
        wc.x += d.x; wc.y += d.y; wc.z += d.z; wc.w += d.w;
        if (l == ROOT_LEVEL) {  // this node is uniquely owned by this block
            float br = fmaxf(heights[node] - heights[(node - 1) >> 1], MIN_DIST);
            acc += (double)((d.x * d.x + d.y * d.y + d.z * d.z + d.w * d.w) / br);
        }
    }

    // DFS over 32 leaves with a 5-deep register stack: every subtree delta row
    // is loaded exactly once (trailing-zeros prefix sharing).
    float4 ws0, ws1, ws2, ws3, ws4;
    #pragma unroll 1
    for (int j = 0; j < LPB; j++) {
        const int i = bi * LPB + j;
        // Prefetch x row early (independent of stack chain).
        float4 xv = ((const float4*)(x + (size_t)i * DIM))[tid];
        int lead = (j == 0) ? (K - 1) : (__ffs(j) - 1);
        if (lead >= 4) UPD(4, wc,  ws4);
        if (lead >= 3) UPD(3, ws4, ws3);
        if (lead >= 2) UPD(2, ws3, ws2);
        if (lead >= 1) UPD(1, ws2, ws1);
        UPD(0, ws1, ws0);
        pd[j * 128 + tid] = xv.x * ws0.x + xv.y * ws0.y + xv.z * ws0.z + xv.w * ws0.w;
    }

    // Warp-reduce the fused sq accumulator.
    #pragma unroll
    for (int off = 16; off; off >>= 1)
        acc += __shfl_down_sync(0xffffffffu, acc, off);
    int warp = tid >> 5, lane = tid & 31;
    if (lane == 0) sacc[warp] = acc;
    __syncthreads();

    // Batched dot reductions: warp w reduces leaves [8w, 8w+8).
    #pragma unroll 1
    for (int j = warp * 8; j < warp * 8 + 8; j++) {
        float v = pd[j * 128 + lane]      + pd[j * 128 + lane + 32]
                + pd[j * 128 + lane + 64] + pd[j * 128 + lane + 96];
        #pragma unroll
        for (int off = 16; off; off >>= 1) v += __shfl_down_sync(0xffffffffu, v, off);
        if (lane == 0) out[bi * LPB + j] = v;
    }

    if (tid == 0) atomicAdd(&g_acc, sacc[0] + sacc[1] + sacc[2] + sacc[3]);
}

__global__ void tm_fin_kernel(float* __restrict__ out) {
    out[N_LEAVES] = (float)g_acc;
}

extern "C" void kernel_launch(void* const* d_in, const int* in_sizes, int n_in,
                              void* d_out, int out_size) {
    const float* x       = (const float*)d_in[0];
    const float* deltas  = (const float*)d_in[1];
    const float* heights = (const float*)d_in[2];
    float* out = (float*)d_out;

    tm_init_kernel<<<1, 1>>>();
    tm_upper_kernel<<<(N_UPPER * 32 + 127) / 128, 128>>>(deltas, heights);
    tm_main_kernel<<<NBLOCKS, 128>>>(x, deltas, heights, out);
    tm_fin_kernel<<<1, 1>>>(out);
}

// round 2
// speedup vs baseline: 1.5565x; 1.5565x over previous
#include <cuda_runtime.h>

#define N_LEAVES   16384
#define DIM        512
#define DEPTH      14
#define K          3                       // subtree depth per block -> 8 leaves
#define LPB        (1 << K)                // 8 leaves per block
#define NBLOCKS    (N_LEAVES / LPB)        // 2048
#define ROOT_LEVEL (DEPTH - K)             // 11
#define N_UPPER    ((1 << ROOT_LEVEL) - 1) // 2047 nodes at levels 0..10
#define MIN_DIST   1e-7f

__device__ double        g_acc;    // zero-initialized; reset by last block each run
__device__ unsigned int  g_count;

// Stack update: load delta row of node at depth offset B above the leaf,
// DST = BASE + delta, and accumulate fused sq/branch term.
#define UPD(B, BASE, DST) do {                                                   \
    int node = (i >> (B)) + ((1 << (DEPTH - (B))) - 1);                          \
    float4 d = ((const float4*)(deltas + (size_t)node * DIM))[tid];              \
    DST.x = BASE.x + d.x; DST.y = BASE.y + d.y;                                  \
    DST.z = BASE.z + d.z; DST.w = BASE.w + d.w;                                  \
    float br = fmaxf(heights[node] - heights[(node - 1) >> 1], MIN_DIST);        \
    acc += (double)((d.x * d.x + d.y * d.y + d.z * d.z + d.w * d.w) / br);       \
} while (0)

__global__ void __launch_bounds__(128)
tm_fused_kernel(const float* __restrict__ x,
                const float* __restrict__ deltas,
                const float* __restrict__ heights,
                float* __restrict__ out) {
    __shared__ float  pd[LPB * 128];   // deferred per-leaf dot partials (4 KB)
    __shared__ double sacc[4];

    const int tid = threadIdx.x;       // owns float4 slice [tid*4, tid*4+4)
    const int bi  = blockIdx.x;        // subtree index (level-11 node = bi + 2047)
    double acc = 0.0;

    // Upper-node duty: block bi (< 2047) owns node bi's sq/branch term.
    if (bi < N_UPPER) {
        int node = bi;
        float4 d = ((const float4*)(deltas + (size_t)node * DIM))[tid];
        float sq = d.x * d.x + d.y * d.y + d.z * d.z + d.w * d.w;
        if (node == 0) {
            acc += (double)sq;
        } else {
            float br = fmaxf(heights[node] - heights[(node - 1) >> 1], MIN_DIST);
            acc += (double)(sq / br);
        }
    }

    // Common path: levels 0..ROOT_LEVEL summed once into registers.
    float4 wc = make_float4(0.f, 0.f, 0.f, 0.f);
    #pragma unroll
    for (int l = 0; l <= ROOT_LEVEL; l++) {
        int node = (bi >> (ROOT_LEVEL - l)) + ((1 << l) - 1);
        float4 d = ((const float4*)(deltas + (size_t)node * DIM))[tid];
        wc.x += d.x; wc.y += d.y; wc.z += d.z; wc.w += d.w;
        if (l == ROOT_LEVEL) {  // level-11 node uniquely owned by this block
            float br = fmaxf(heights[node] - heights[(node - 1) >> 1], MIN_DIST);
            acc += (double)((d.x * d.x + d.y * d.y + d.z * d.z + d.w * d.w) / br);
        }
    }

    // DFS over 8 leaves, 3-deep register stack, fully unrolled: lead is
    // compile-time, so all 14 delta + 8 x loads can be front-batched (MLP).
    float4 ws0, ws1, ws2;
    #pragma unroll
    for (int j = 0; j < LPB; j++) {
        const int i = bi * LPB + j;
        float4 xv = ((const float4*)(x + (size_t)i * DIM))[tid];
        const int lead = (j == 0) ? (K - 1) : (__builtin_ffs(j) - 1);
        if (lead >= 2) UPD(2, wc,  ws2);
        if (lead >= 1) UPD(1, ws2, ws1);
        UPD(0, ws1, ws0);
        pd[j * 128 + tid] = xv.x * ws0.x + xv.y * ws0.y + xv.z * ws0.z + xv.w * ws0.w;
    }

    // Reduce fused sq accumulator across the block.
    #pragma unroll
    for (int off = 16; off; off >>= 1)
        acc += __shfl_down_sync(0xffffffffu, acc, off);
    int warp = tid >> 5, lane = tid & 31;
    if (lane == 0) sacc[warp] = acc;
    __syncthreads();

    // Batched dot reductions: warp w reduces leaves [2w, 2w+2).
    #pragma unroll
    for (int j = warp * 2; j < warp * 2 + 2; j++) {
        float v = pd[j * 128 + lane]      + pd[j * 128 + lane + 32]
                + pd[j * 128 + lane + 64] + pd[j * 128 + lane + 96];
        #pragma unroll
        for (int off = 16; off; off >>= 1) v += __shfl_down_sync(0xffffffffu, v, off);
        if (lane == 0) out[bi * LPB + j] = v;
    }

    // Scalar epilogue: last block to finish writes delta_total and resets state.
    if (tid == 0) {
        atomicAdd(&g_acc, sacc[0] + sacc[1] + sacc[2] + sacc[3]);
        __threadfence();
        unsigned int prev = atomicAdd(&g_count, 1u);
        if (prev == (unsigned int)(gridDim.x - 1)) {
            out[N_LEAVES] = (float)(*(volatile double*)&g_acc);
            g_acc   = 0.0;   // graph-replay safe: reset for the next invocation
            g_count = 0u;
        }
    }
}

extern "C" void kernel_launch(void* const* d_in, const int* in_sizes, int n_in,
                              void* d_out, int out_size) {
    const float* x       = (const float*)d_in[0];
    const float* deltas  = (const float*)d_in[1];
    const float* heights = (const float*)d_in[2];
    float* out = (float*)d_out;

    tm_fused_kernel<<<NBLOCKS, 128>>>(x, deltas, heights, out);
}

// round 3
// speedup vs baseline: 2.4861x; 1.5972x over previous
#include <cuda_runtime.h>

#define N_LEAVES   16384
#define DIM        512
#define DEPTH      14
#define K          3                       // subtree depth per block -> 8 leaves
#define LPB        (1 << K)                // 8 leaves per block
#define NBLOCKS    (N_LEAVES / LPB)        // 2048
#define ROOT_LEVEL (DEPTH - K)             // 11
#define N_UPPER    ((1 << ROOT_LEVEL) - 1) // 2047 nodes at levels 0..10
#define MIN_DIST   1e-7f

__device__ double        g_acc;    // zero-init; reset by last block each run
__device__ unsigned int  g_count;

__device__ __forceinline__ float sq4(float4 d) {
    return d.x * d.x + d.y * d.y + d.z * d.z + d.w * d.w;
}

__global__ void __launch_bounds__(128, 8)
tm_fused_kernel(const float* __restrict__ x,
                const float* __restrict__ deltas,
                const float* __restrict__ heights,
                float* __restrict__ out) {
    __shared__ float  pd[LPB * 128];   // deferred per-leaf dot partials (4 KB)
    __shared__ double sacc[4];

    const int tid = threadIdx.x;       // owns float4 slice [tid*4, tid*4+4)
    const int bi  = blockIdx.x;        // subtree index (level-11 node = bi + 2047)
    float facc = 0.f;                  // per-thread sq/branch partial (float)

    // Upper-node duty: block bi (< 2047) owns node bi's sq/branch term.
    if (bi < N_UPPER) {
        float4 d = ((const float4*)(deltas + (size_t)bi * DIM))[tid];
        float s = sq4(d);
        if (bi == 0) facc += s;
        else facc += __fdividef(s, fmaxf(heights[bi] - heights[(bi - 1) >> 1], MIN_DIST));
    }

    // Common path: levels 0..ROOT_LEVEL summed once (independent loads).
    float4 wc = make_float4(0.f, 0.f, 0.f, 0.f);
    #pragma unroll
    for (int l = 0; l <= ROOT_LEVEL; l++) {
        int node = (bi >> (ROOT_LEVEL - l)) + ((1 << l) - 1);
        float4 d = ((const float4*)(deltas + (size_t)node * DIM))[tid];
        wc.x += d.x; wc.y += d.y; wc.z += d.z; wc.w += d.w;
        if (l == ROOT_LEVEL) {  // level-11 node uniquely owned by this block
            facc += __fdividef(sq4(d),
                fmaxf(heights[node] - heights[(node - 1) >> 1], MIN_DIST));
        }
    }

    // Flat per-leaf loads: 4 fully independent LDG.128 per leaf, no carried
    // dependency chain. Level-13/12 rows are re-loaded (L1 hits), so unique
    // L2/DRAM traffic is unchanged while MLP is maximized.
    #pragma unroll
    for (int j = 0; j < LPB; j++) {
        const int i   = bi * LPB + j;
        const int n_c = i + (N_LEAVES - 1);          // level 14 (leaf)
        const int n_b = (i >> 1) + (N_LEAVES / 2 - 1); // level 13
        const int n_a = (i >> 2) + (N_LEAVES / 4 - 1); // level 12

        float4 xv = ((const float4*)(x      + (size_t)i   * DIM))[tid];
        float4 da = ((const float4*)(deltas + (size_t)n_a * DIM))[tid];
        float4 db = ((const float4*)(deltas + (size_t)n_b * DIM))[tid];
        float4 dc = ((const float4*)(deltas + (size_t)n_c * DIM))[tid];

        float tx = wc.x + da.x + db.x + dc.x;
        float ty = wc.y + da.y + db.y + dc.y;
        float tz = wc.z + da.z + db.z + dc.z;
        float tw = wc.w + da.w + db.w + dc.w;
        pd[j * 128 + tid] = xv.x * tx + xv.y * ty + xv.z * tz + xv.w * tw;

        // sq/branch: count each node exactly once (guards on j).
        facc += __fdividef(sq4(dc),
            fmaxf(heights[n_c] - heights[n_b], MIN_DIST));
        if ((j & 1) == 0)
            facc += __fdividef(sq4(db),
                fmaxf(heights[n_b] - heights[n_a], MIN_DIST));
        if ((j & 3) == 0)
            facc += __fdividef(sq4(da),
                fmaxf(heights[n_a] - heights[(n_a - 1) >> 1], MIN_DIST));
    }

    // Reduce fused sq accumulator across the block (double from here on).
    double acc = (double)facc;
    #pragma unroll
    for (int off = 16; off; off >>= 1)
        acc += __shfl_down_sync(0xffffffffu, acc, off);
    int warp = tid >> 5, lane = tid & 31;
    if (lane == 0) sacc[warp] = acc;
    __syncthreads();

    // Batched dot reductions: warp w reduces leaves [2w, 2w+2).
    #pragma unroll
    for (int j = warp * 2; j < warp * 2 + 2; j++) {
        float v = pd[j * 128 + lane]      + pd[j * 128 + lane + 32]
                + pd[j * 128 + lane + 64] + pd[j * 128 + lane + 96];
        #pragma unroll
        for (int off = 16; off; off >>= 1) v += __shfl_down_sync(0xffffffffu, v, off);
        if (lane == 0) out[bi * LPB + j] = v;
    }

    // Scalar epilogue: last block writes delta_total and resets state.
    if (tid == 0) {
        atomicAdd(&g_acc, sacc[0] + sacc[1] + sacc[2] + sacc[3]);
        __threadfence();
        unsigned int prev = atomicAdd(&g_count, 1u);
        if (prev == (unsigned int)(gridDim.x - 1)) {
            out[N_LEAVES] = (float)(*(volatile double*)&g_acc);
            g_acc   = 0.0;   // graph-replay safe
            g_count = 0u;
        }
    }
}

extern "C" void kernel_launch(void* const* d_in, const int* in_sizes, int n_in,
                              void* d_out, int out_size) {
    const float* x       = (const float*)d_in[0];
    const float* deltas  = (const float*)d_in[1];
    const float* heights = (const float*)d_in[2];
    float* out = (float*)d_out;

    tm_fused_kernel<<<NBLOCKS, 128>>>(x, deltas, heights, out);
}